// round 4
// baseline (speedup 1.0000x reference)
#include <cuda_runtime.h>

typedef unsigned long long ull;

// ---------------- scratch (device globals; no allocations allowed) ----------
__device__ float g_pooled1[8*2*64*64*64];   // 16 MB  [n][c][h][w][t]
__device__ float g_h0     [8*4*64*64*64];   // 32 MB  [n][co][h][w][t]
__device__ float g_pooled2[8*4*16*16*64];   //  2 MB  [n][c][H][W][t]
__device__ float g_h1     [8*8*16*16*64];   //  4 MB  [n][co][H][W][t]
__device__ float g_pooled3[8*8*4*4*64];     // 256 KB [n][c][h3][w3][t]

// ---------------- packed f32x2 helpers (sm_103a) ----------------------------
__device__ __forceinline__ ull fma2(ull a, ull b, ull c) {
    ull d;
    asm("fma.rn.f32x2 %0, %1, %2, %3;" : "=l"(d) : "l"(a), "l"(b), "l"(c));
    return d;
}
__device__ __forceinline__ ull bcast2(float x) {
    unsigned u = __float_as_uint(x);
    return (ull)u | ((ull)u << 32);
}

// ---------------- K1: avgpool4 (8,2,256,256,64) -> (8,2,64,64,64) -----------
// thread = (nc, h, w, t4); lanes cover consecutive t4 -> fully coalesced.
__global__ void __launch_bounds__(256) pool1_kernel(const float* __restrict__ inp) {
    int idx = blockIdx.x * 256 + threadIdx.x;          // 1,048,576 exact
    int t4 = idx & 15;
    int w  = (idx >> 4)  & 63;
    int h  = (idx >> 10) & 63;
    int nc = idx >> 16;                                 // n*2+c in [0,16)
    const float* base = inp + ((size_t)nc * 256 * 256 + (h * 4) * 256 + (w * 4)) * 64 + t4 * 4;
    float4 s = make_float4(0.f, 0.f, 0.f, 0.f);
#pragma unroll
    for (int dy = 0; dy < 4; dy++) {
#pragma unroll
        for (int dx = 0; dx < 4; dx++) {
            float4 v = *(const float4*)(base + (dy * 256 + dx) * 64);
            s.x += v.x; s.y += v.y; s.z += v.z; s.w += v.w;
        }
    }
    s.x *= 0.0625f; s.y *= 0.0625f; s.z *= 0.0625f; s.w *= 0.0625f;
    *(float4*)(g_pooled1 + ((size_t)nc * 64 * 64 + h * 64 + w) * 64 + t4 * 4) = s;
}

// ---------------- K2: conv7x7 pad3, 2->4 ch, on (*,2,64,64) x t -------------
// block = (32 t-pairs, 8 w); thread computes acc[4 co][8 h] in packed f32x2.
// grid (w/8=8, h/8=8, n=8)
__global__ void __launch_bounds__(256) conv1_kernel(const float* __restrict__ w0) {
    __shared__ ull sw[4][2][49];
    int tid = threadIdx.y * 32 + threadIdx.x;
    for (int i = tid; i < 4 * 2 * 49; i += 256) ((ull*)sw)[i] = bcast2(w0[i]);
    __syncthreads();

    int tp = threadIdx.x;                    // t-pair 0..31
    int w  = blockIdx.x * 8 + threadIdx.y;   // 0..63
    int hb = blockIdx.y * 8;
    int n  = blockIdx.z;

    ull acc[4][8];
#pragma unroll
    for (int a = 0; a < 4; a++)
#pragma unroll
        for (int b = 0; b < 8; b++) acc[a][b] = 0ull;

    for (int ci = 0; ci < 2; ci++) {
        const float* base = g_pooled1 + (size_t)(n * 2 + ci) * 4096 * 64;
#pragma unroll
        for (int r = 0; r < 14; r++) {               // input rows hb-3 .. hb+10
            int R = hb - 3 + r;
            if ((unsigned)R >= 64u) continue;
#pragma unroll
            for (int kx = 0; kx < 7; kx++) {
                int iw = w + kx - 3;
                if ((unsigned)iw >= 64u) continue;
                ull v = *(const ull*)(base + (R * 64 + iw) * 64 + tp * 2);
#pragma unroll
                for (int ky = 0; ky < 7; ky++) {
                    int hl = r - ky;                 // compile-time per (r,ky)
                    if (hl < 0 || hl >= 8) continue;
#pragma unroll
                    for (int co = 0; co < 4; co++)
                        acc[co][hl] = fma2(v, sw[co][ci][ky * 7 + kx], acc[co][hl]);
                }
            }
        }
    }
#pragma unroll
    for (int co = 0; co < 4; co++)
#pragma unroll
        for (int hl = 0; hl < 8; hl++)
            *(ull*)(g_h0 + (size_t)(((n * 4 + co) * 64 + hb + hl) * 64 + w) * 64 + tp * 2) = acc[co][hl];
}

// ---------------- K3: IAF (membrane-subtract) + avgpool4, stage 1 -----------
// warp handles two 4x4 pixel groups; each lane scans its pixel over t=64;
// per-t spike sum reduced over 16 lanes with shfl_xor.
__global__ void __launch_bounds__(256) iaf1_pool2_kernel() {
    int warp_id = blockIdx.x * 8 + (threadIdx.x >> 5);
    int lane = threadIdx.x & 31;
    int g = warp_id * 2 + (lane >> 4);               // group in [0, 8192)
    int Wg = g & 15, Hg = (g >> 4) & 15, c = (g >> 8) & 3, n = g >> 10;
    int l = lane & 15;
    int h = Hg * 4 + (l >> 2), w = Wg * 4 + (l & 3);
    const float* src = g_h0 + (size_t)(((n * 4 + c) * 64 + h) * 64 + w) * 64;
    float* dst = g_pooled2 + (size_t)(((n * 4 + c) * 16 + Hg) * 16 + Wg) * 64;

    float v = 0.f;
    for (int tb = 0; tb < 16; tb++) {
        float4 x = *(const float4*)(src + tb * 4);
        float xv[4] = {x.x, x.y, x.z, x.w};
#pragma unroll
        for (int k = 0; k < 4; k++) {
            v += xv[k];
            float s = (v >= 1.f) ? 1.f : 0.f;
            v -= s;
            s += __shfl_xor_sync(0xffffffffu, s, 1);
            s += __shfl_xor_sync(0xffffffffu, s, 2);
            s += __shfl_xor_sync(0xffffffffu, s, 4);
            s += __shfl_xor_sync(0xffffffffu, s, 8);
            if (l == 0) dst[tb * 4 + k] = s * 0.0625f;
        }
    }
}

// ---------------- K4: conv7x7 pad3, 4->8 ch, on (*,4,16,16) x t -------------
// block = (32 t-pairs, 8 w); acc[4 co][4 h]; grid (16/8=2, 16/4=4, n*2=16)
__global__ void __launch_bounds__(256) conv2_kernel(const float* __restrict__ w1) {
    __shared__ ull sw[4][4][49];
    int n = blockIdx.z >> 1;
    int cobase = (blockIdx.z & 1) * 4;
    int tid = threadIdx.y * 32 + threadIdx.x;
    for (int i = tid; i < 4 * 4 * 49; i += 256) ((ull*)sw)[i] = bcast2(w1[cobase * 196 + i]);
    __syncthreads();

    int tp = threadIdx.x;
    int w  = blockIdx.x * 8 + threadIdx.y;   // 0..15
    int hb = blockIdx.y * 4;

    ull acc[4][4];
#pragma unroll
    for (int a = 0; a < 4; a++)
#pragma unroll
        for (int b = 0; b < 4; b++) acc[a][b] = 0ull;

    for (int ci = 0; ci < 4; ci++) {
        const float* base = g_pooled2 + (size_t)(n * 4 + ci) * 256 * 64;
#pragma unroll
        for (int r = 0; r < 10; r++) {
            int R = hb - 3 + r;
            if ((unsigned)R >= 16u) continue;
#pragma unroll
            for (int kx = 0; kx < 7; kx++) {
                int iw = w + kx - 3;
                if ((unsigned)iw >= 16u) continue;
                ull v = *(const ull*)(base + (R * 16 + iw) * 64 + tp * 2);
#pragma unroll
                for (int ky = 0; ky < 7; ky++) {
                    int hl = r - ky;
                    if (hl < 0 || hl >= 4) continue;
#pragma unroll
                    for (int co = 0; co < 4; co++)
                        acc[co][hl] = fma2(v, sw[co][ci][ky * 7 + kx], acc[co][hl]);
                }
            }
        }
    }
#pragma unroll
    for (int co = 0; co < 4; co++)
#pragma unroll
        for (int hl = 0; hl < 4; hl++)
            *(ull*)(g_h1 + (size_t)(((n * 8 + cobase + co) * 16 + hb + hl) * 16 + w) * 64 + tp * 2) = acc[co][hl];
}

// ---------------- K5: IAF + avgpool4, stage 2 --------------------------------
__global__ void __launch_bounds__(256) iaf2_pool3_kernel() {
    int warp_id = blockIdx.x * 8 + (threadIdx.x >> 5);
    int lane = threadIdx.x & 31;
    int g = warp_id * 2 + (lane >> 4);               // group in [0, 1024)
    int Wg = g & 3, Hg = (g >> 2) & 3, c = (g >> 4) & 7, n = g >> 7;
    int l = lane & 15;
    int h = Hg * 4 + (l >> 2), w = Wg * 4 + (l & 3);
    const float* src = g_h1 + (size_t)(((n * 8 + c) * 16 + h) * 16 + w) * 64;
    float* dst = g_pooled3 + (size_t)(((n * 8 + c) * 4 + Hg) * 4 + Wg) * 64;

    float v = 0.f;
    for (int tb = 0; tb < 16; tb++) {
        float4 x = *(const float4*)(src + tb * 4);
        float xv[4] = {x.x, x.y, x.z, x.w};
#pragma unroll
        for (int k = 0; k < 4; k++) {
            v += xv[k];
            float s = (v >= 1.f) ? 1.f : 0.f;
            v -= s;
            s += __shfl_xor_sync(0xffffffffu, s, 1);
            s += __shfl_xor_sync(0xffffffffu, s, 2);
            s += __shfl_xor_sync(0xffffffffu, s, 4);
            s += __shfl_xor_sync(0xffffffffu, s, 8);
            if (l == 0) dst[tb * 4 + k] = s * 0.0625f;
        }
    }
}

// ---------------- K6: feat(128) @ wl.T -> out (n,2,t) ------------------------
__global__ void __launch_bounds__(512) linear_kernel(const float* __restrict__ wl,
                                                     float* __restrict__ out) {
    int tid = threadIdx.x;
    __shared__ float swl[256];
    if (tid < 256) swl[tid] = wl[tid];
    __syncthreads();
    int t = tid & 63;
    int n = tid >> 6;
    const float* p = g_pooled3 + n * 128 * 64 + t;
    float a0 = 0.f, a1 = 0.f;
#pragma unroll
    for (int f = 0; f < 128; f++) {
        float v = p[f * 64];
        a0 += v * swl[f];
        a1 += v * swl[128 + f];
    }
    out[(n * 2 + 0) * 64 + t] = a0;
    out[(n * 2 + 1) * 64 + t] = a1;
}

// ---------------- launch ------------------------------------------------------
extern "C" void kernel_launch(void* const* d_in, const int* in_sizes, int n_in,
                              void* d_out, int out_size) {
    const float* inp = (const float*)d_in[0];   // (8,2,256,256,64)
    const float* w0  = (const float*)d_in[1];   // (4,2,7,7)
    const float* w1  = (const float*)d_in[2];   // (8,4,7,7)
    const float* wl  = (const float*)d_in[3];   // (2,128)
    float* out = (float*)d_out;                 // (8,2,64)

    pool1_kernel   <<<4096, 256>>>(inp);
    conv1_kernel   <<<dim3(8, 8, 8),  dim3(32, 8)>>>(w0);
    iaf1_pool2_kernel<<<512, 256>>>();
    conv2_kernel   <<<dim3(2, 4, 16), dim3(32, 8)>>>(w1);
    iaf2_pool3_kernel<<<64, 256>>>();
    linear_kernel  <<<1, 512>>>(wl, out);
}

// round 6
// speedup vs baseline: 1.0604x; 1.0604x over previous
#include <cuda_runtime.h>

typedef unsigned long long ull;

// ---------------- scratch (device globals; no allocations allowed) ----------
__device__ float g_pooled1[8*2*64*64*64];   // 16 MB  [n][c][h][w][t]
__device__ float g_h0     [8*4*64*64*64];   // 32 MB  [n][co][h][w][t]
__device__ float g_pooled2[8*4*16*16*64];   //  2 MB  [n][c][H][W][t]
__device__ float g_h1     [8*8*16*16*64];   //  4 MB  [n][co][H][W][t]
__device__ float g_pooled3[8*8*4*4*64];     // 256 KB [n][c][h3][w3][t]

// ---------------- packed f32x2 helpers (sm_103a) ----------------------------
__device__ __forceinline__ ull fma2(ull a, ull b, ull c) {
    ull d;
    asm("fma.rn.f32x2 %0, %1, %2, %3;" : "=l"(d) : "l"(a), "l"(b), "l"(c));
    return d;
}
__device__ __forceinline__ ull bcast2(float x) {
    unsigned u = __float_as_uint(x);
    return (ull)u | ((ull)u << 32);
}

// ---------------- K1: avgpool4 (8,2,256,256,64) -> (8,2,64,64,64) -----------
__global__ void __launch_bounds__(256) pool1_kernel(const float* __restrict__ inp) {
    int idx = blockIdx.x * 256 + threadIdx.x;          // 1,048,576 exact
    int t4 = idx & 15;
    int w  = (idx >> 4)  & 63;
    int h  = (idx >> 10) & 63;
    int nc = idx >> 16;                                 // n*2+c in [0,16)
    const float* base = inp + ((size_t)nc * 256 * 256 + (h * 4) * 256 + (w * 4)) * 64 + t4 * 4;
    float4 s = make_float4(0.f, 0.f, 0.f, 0.f);
#pragma unroll
    for (int dy = 0; dy < 4; dy++) {
#pragma unroll
        for (int dx = 0; dx < 4; dx++) {
            float4 v = *(const float4*)(base + (dy * 256 + dx) * 64);
            s.x += v.x; s.y += v.y; s.z += v.z; s.w += v.w;
        }
    }
    s.x *= 0.0625f; s.y *= 0.0625f; s.z *= 0.0625f; s.w *= 0.0625f;
    *(float4*)(g_pooled1 + ((size_t)nc * 64 * 64 + h * 64 + w) * 64 + t4 * 4) = s;
}

// ---------------- K2: conv7x7 pad3, 2->4 ch, on (*,2,64,64) x t -------------
// block = (32 t-pairs, 8 w); thread computes acc[4 co][4 h] packed f32x2.
// grid (64/8=8 wtiles, 64/4=16 htiles, n=8) = 1024 blocks
__global__ void __launch_bounds__(256) conv1_kernel(const float* __restrict__ w0) {
    __shared__ ull sw[4][2][49];
    int tid = threadIdx.y * 32 + threadIdx.x;
    for (int i = tid; i < 4 * 2 * 49; i += 256) ((ull*)sw)[i] = bcast2(w0[i]);
    __syncthreads();

    int tp = threadIdx.x;                    // t-pair 0..31
    int w  = blockIdx.x * 8 + threadIdx.y;   // 0..63
    int hb = blockIdx.y * 4;
    int n  = blockIdx.z;

    ull acc[4][4];
#pragma unroll
    for (int a = 0; a < 4; a++)
#pragma unroll
        for (int b = 0; b < 4; b++) acc[a][b] = 0ull;

#pragma unroll
    for (int ci = 0; ci < 2; ci++) {
        const float* base = g_pooled1 + (size_t)(n * 2 + ci) * 4096 * 64;
#pragma unroll
        for (int r = 0; r < 10; r++) {               // input rows hb-3 .. hb+6
            int R = hb - 3 + r;
            if ((unsigned)R >= 64u) continue;
#pragma unroll
            for (int kx = 0; kx < 7; kx++) {
                int iw = w + kx - 3;
                if ((unsigned)iw >= 64u) continue;
                ull v = *(const ull*)(base + (R * 64 + iw) * 64 + tp * 2);
#pragma unroll
                for (int ky = 0; ky < 7; ky++) {
                    int hl = r - ky;                 // compile-time per (r,ky)
                    if (hl < 0 || hl >= 4) continue;
#pragma unroll
                    for (int co = 0; co < 4; co++)
                        acc[co][hl] = fma2(v, sw[co][ci][ky * 7 + kx], acc[co][hl]);
                }
            }
        }
    }
#pragma unroll
    for (int co = 0; co < 4; co++)
#pragma unroll
        for (int hl = 0; hl < 4; hl++)
            *(ull*)(g_h0 + (size_t)(((n * 4 + co) * 64 + hb + hl) * 64 + w) * 64 + tp * 2) = acc[co][hl];
}

// ---------------- K3: IAF (membrane-subtract) + avgpool4, stage 1 -----------
// warp = two 4x4 pixel groups (16 lanes each); lane scans its pixel over t=64.
// 4 timesteps' spikes packed into one int (5-bit fields) before shfl reduce.
__global__ void __launch_bounds__(256) iaf1_pool2_kernel() {
    int warp_id = blockIdx.x * 8 + (threadIdx.x >> 5);
    int lane = threadIdx.x & 31;
    int g = warp_id * 2 + (lane >> 4);               // group in [0, 8192)
    int Wg = g & 15, Hg = (g >> 4) & 15, c = (g >> 8) & 3, n = g >> 10;
    int l = lane & 15;
    int h = Hg * 4 + (l >> 2), w = Wg * 4 + (l & 3);
    const float* src = g_h0 + (size_t)(((n * 4 + c) * 64 + h) * 64 + w) * 64;
    float* dst = g_pooled2 + (size_t)(((n * 4 + c) * 16 + Hg) * 16 + Wg) * 64;

    float v = 0.f;
#pragma unroll
    for (int tb = 0; tb < 16; tb++) {
        float4 x = *(const float4*)(src + tb * 4);
        float xv[4] = {x.x, x.y, x.z, x.w};
        int packed = 0;
#pragma unroll
        for (int k = 0; k < 4; k++) {
            v += xv[k];
            float s = (v >= 1.f) ? 1.f : 0.f;
            v -= s;
            packed |= (int)s << (5 * k);
        }
        // reduce over 16-lane group; fields max 16 < 32, no cross-field carry
        packed += __shfl_xor_sync(0xffffffffu, packed, 1);
        packed += __shfl_xor_sync(0xffffffffu, packed, 2);
        packed += __shfl_xor_sync(0xffffffffu, packed, 4);
        packed += __shfl_xor_sync(0xffffffffu, packed, 8);
        if (l == 0) {
            float4 o;
            o.x = (float)( packed        & 31) * 0.0625f;
            o.y = (float)((packed >> 5)  & 31) * 0.0625f;
            o.z = (float)((packed >> 10) & 31) * 0.0625f;
            o.w = (float)((packed >> 15) & 31) * 0.0625f;
            *(float4*)(dst + tb * 4) = o;
        }
    }
}

// ---------------- K4: conv7x7 pad3, 4->8 ch, on (*,4,16,16) x t -------------
// block = (32 t-pairs, 4 w); thread computes acc[8 co][1 h].
// grid (16/4=4 wtiles, 16 h, 8 n) = 512 blocks of 128 threads
__global__ void __launch_bounds__(128) conv2_kernel(const float* __restrict__ w1) {
    __shared__ ull sw[8][4][49];
    int tid = threadIdx.y * 32 + threadIdx.x;
    for (int i = tid; i < 8 * 4 * 49; i += 128) ((ull*)sw)[i] = bcast2(w1[i]);
    __syncthreads();

    int tp = threadIdx.x;
    int w  = blockIdx.x * 4 + threadIdx.y;   // 0..15
    int h  = blockIdx.y;                     // 0..15
    int n  = blockIdx.z;

    ull acc[8];
#pragma unroll
    for (int a = 0; a < 8; a++) acc[a] = 0ull;

#pragma unroll
    for (int ci = 0; ci < 4; ci++) {
        const float* base = g_pooled2 + (size_t)(n * 4 + ci) * 256 * 64;
#pragma unroll
        for (int r = 0; r < 7; r++) {                // ky = r, input row h-3+r
            int R = h - 3 + r;
            if ((unsigned)R >= 16u) continue;
#pragma unroll
            for (int kx = 0; kx < 7; kx++) {
                int iw = w + kx - 3;
                if ((unsigned)iw >= 16u) continue;
                ull v = *(const ull*)(base + (R * 16 + iw) * 64 + tp * 2);
#pragma unroll
                for (int co = 0; co < 8; co++)
                    acc[co] = fma2(v, sw[co][ci][r * 7 + kx], acc[co]);
            }
        }
    }
#pragma unroll
    for (int co = 0; co < 8; co++)
        *(ull*)(g_h1 + (size_t)(((n * 8 + co) * 16 + h) * 16 + w) * 64 + tp * 2) = acc[co];
}

// ---------------- K5: IAF + avgpool4, stage 2 --------------------------------
__global__ void __launch_bounds__(256) iaf2_pool3_kernel() {
    int warp_id = blockIdx.x * 8 + (threadIdx.x >> 5);
    int lane = threadIdx.x & 31;
    int g = warp_id * 2 + (lane >> 4);               // group in [0, 1024)
    int Wg = g & 3, Hg = (g >> 2) & 3, c = (g >> 4) & 7, n = g >> 7;
    int l = lane & 15;
    int h = Hg * 4 + (l >> 2), w = Wg * 4 + (l & 3);
    const float* src = g_h1 + (size_t)(((n * 8 + c) * 16 + h) * 16 + w) * 64;
    float* dst = g_pooled3 + (size_t)(((n * 8 + c) * 4 + Hg) * 4 + Wg) * 64;

    float v = 0.f;
#pragma unroll
    for (int tb = 0; tb < 16; tb++) {
        float4 x = *(const float4*)(src + tb * 4);
        float xv[4] = {x.x, x.y, x.z, x.w};
        int packed = 0;
#pragma unroll
        for (int k = 0; k < 4; k++) {
            v += xv[k];
            float s = (v >= 1.f) ? 1.f : 0.f;
            v -= s;
            packed |= (int)s << (5 * k);
        }
        packed += __shfl_xor_sync(0xffffffffu, packed, 1);
        packed += __shfl_xor_sync(0xffffffffu, packed, 2);
        packed += __shfl_xor_sync(0xffffffffu, packed, 4);
        packed += __shfl_xor_sync(0xffffffffu, packed, 8);
        if (l == 0) {
            float4 o;
            o.x = (float)( packed        & 31) * 0.0625f;
            o.y = (float)((packed >> 5)  & 31) * 0.0625f;
            o.z = (float)((packed >> 10) & 31) * 0.0625f;
            o.w = (float)((packed >> 15) & 31) * 0.0625f;
            *(float4*)(dst + tb * 4) = o;
        }
    }
}

// ---------------- K6: feat(128) @ wl.T -> out (n,2,t) ------------------------
__global__ void __launch_bounds__(512) linear_kernel(const float* __restrict__ wl,
                                                     float* __restrict__ out) {
    int tid = threadIdx.x;
    __shared__ float swl[256];
    if (tid < 256) swl[tid] = wl[tid];
    __syncthreads();
    int t = tid & 63;
    int n = tid >> 6;
    const float* p = g_pooled3 + n * 128 * 64 + t;
    float a0 = 0.f, a1 = 0.f;
#pragma unroll
    for (int f = 0; f < 128; f++) {
        float v = p[f * 64];
        a0 += v * swl[f];
        a1 += v * swl[128 + f];
    }
    out[(n * 2 + 0) * 64 + t] = a0;
    out[(n * 2 + 1) * 64 + t] = a1;
}

// ---------------- launch ------------------------------------------------------
extern "C" void kernel_launch(void* const* d_in, const int* in_sizes, int n_in,
                              void* d_out, int out_size) {
    const float* inp = (const float*)d_in[0];   // (8,2,256,256,64)
    const float* w0  = (const float*)d_in[1];   // (4,2,7,7)
    const float* w1  = (const float*)d_in[2];   // (8,4,7,7)
    const float* wl  = (const float*)d_in[3];   // (2,128)
    float* out = (float*)d_out;                 // (8,2,64)

    pool1_kernel     <<<4096, 256>>>(inp);
    conv1_kernel     <<<dim3(8, 16, 8), dim3(32, 8)>>>(w0);
    iaf1_pool2_kernel<<<512, 256>>>();
    conv2_kernel     <<<dim3(4, 16, 8), dim3(32, 4)>>>(w1);
    iaf2_pool3_kernel<<<64, 256>>>();
    linear_kernel    <<<1, 512>>>(wl, out);
}

// round 7
// speedup vs baseline: 1.5903x; 1.4998x over previous
#include <cuda_runtime.h>

typedef unsigned long long ull;

// ---------------- scratch (device globals; zero-initialized at load) --------
// Padded layouts: halo of 3 on each side, never written -> stays zero.
__device__ float g_pooled1p[8*2*70*70*64];  // 20 MB [n][c][70][70][t] (pad 3)
__device__ float g_h0      [8*4*64*64*64];  // 32 MB [n][co][h][w][t]
__device__ float g_pooled2p[8*4*22*22*64];  //  4 MB [n][c][22][22][t] (pad 3)
__device__ float g_h1a     [8*8*16*16*64];  //  4 MB partial (ci 0,1)
__device__ float g_h1b     [8*8*16*16*64];  //  4 MB partial (ci 2,3)
__device__ float g_pooled3 [8*8*4*4*64];    // 256 KB [n][c][h3][w3][t]

// ---------------- packed f32x2 helpers (sm_103a) ----------------------------
__device__ __forceinline__ ull fma2(ull a, ull b, ull c) {
    ull d;
    asm("fma.rn.f32x2 %0, %1, %2, %3;" : "=l"(d) : "l"(a), "l"(b), "l"(c));
    return d;
}
__device__ __forceinline__ ull bcast2(float x) {
    unsigned u = __float_as_uint(x);
    return (ull)u | ((ull)u << 32);
}

// ---------------- K1: avgpool4 (8,2,256,256,64) -> padded (8,2,70,70,64) ----
__global__ void __launch_bounds__(256) pool1_kernel(const float* __restrict__ inp) {
    int idx = blockIdx.x * 256 + threadIdx.x;          // 1,048,576 exact
    int t4 = idx & 15;
    int w  = (idx >> 4)  & 63;
    int h  = (idx >> 10) & 63;
    int nc = idx >> 16;                                 // n*2+c in [0,16)
    const float* base = inp + ((size_t)nc * 256 * 256 + (h * 4) * 256 + (w * 4)) * 64 + t4 * 4;
    float4 s = make_float4(0.f, 0.f, 0.f, 0.f);
#pragma unroll
    for (int dy = 0; dy < 4; dy++) {
#pragma unroll
        for (int dx = 0; dx < 4; dx++) {
            float4 v = *(const float4*)(base + (dy * 256 + dx) * 64);
            s.x += v.x; s.y += v.y; s.z += v.z; s.w += v.w;
        }
    }
    s.x *= 0.0625f; s.y *= 0.0625f; s.z *= 0.0625f; s.w *= 0.0625f;
    *(float4*)(g_pooled1p + (((size_t)nc * 70 + h + 3) * 70 + w + 3) * 64 + t4 * 4) = s;
}

// ---------------- K2: conv7x7 pad3, 2->4 ch, 64x64, padded input ------------
// block = (32 t-pairs, 8 w); thread computes acc[4 co][4 h] packed f32x2.
// grid (8 wtiles, 16 htiles, 8 n) = 1024 blocks. All loads unconditional.
__global__ void __launch_bounds__(256) conv1_kernel(const float* __restrict__ w0) {
    __shared__ ull sw[4][2][49];
    int tid = threadIdx.y * 32 + threadIdx.x;
    for (int i = tid; i < 4 * 2 * 49; i += 256) ((ull*)sw)[i] = bcast2(w0[i]);
    __syncthreads();

    int tp = threadIdx.x;                    // t-pair 0..31
    int w  = blockIdx.x * 8 + threadIdx.y;   // 0..63
    int hb = blockIdx.y * 4;
    int n  = blockIdx.z;

    ull acc[4][4];
#pragma unroll
    for (int a = 0; a < 4; a++)
#pragma unroll
        for (int b = 0; b < 4; b++) acc[a][b] = 0ull;

#pragma unroll
    for (int ci = 0; ci < 2; ci++) {
        const float* base = g_pooled1p + (size_t)(n * 2 + ci) * 70 * 70 * 64;
#pragma unroll
        for (int r = 0; r < 10; r++) {       // padded rows hb+0 .. hb+9
            const float* rowp = base + (((hb + r) * 70) + w) * 64 + tp * 2;
            ull v[7];
#pragma unroll
            for (int kx = 0; kx < 7; kx++)
                v[kx] = *(const ull*)(rowp + kx * 64);
#pragma unroll
            for (int ky = 0; ky < 7; ky++) {
                int hl = r - ky;             // compile-time per (r,ky)
                if (hl < 0 || hl >= 4) continue;
#pragma unroll
                for (int co = 0; co < 4; co++)
#pragma unroll
                    for (int kx = 0; kx < 7; kx++)
                        acc[co][hl] = fma2(v[kx], sw[co][ci][ky * 7 + kx], acc[co][hl]);
            }
        }
    }
#pragma unroll
    for (int co = 0; co < 4; co++)
#pragma unroll
        for (int hl = 0; hl < 4; hl++)
            *(ull*)(g_h0 + (size_t)(((n * 4 + co) * 64 + hb + hl) * 64 + w) * 64 + tp * 2) = acc[co][hl];
}

// ---------------- K3: IAF (membrane-subtract) + avgpool4, stage 1 -----------
// warp = two 4x4 pixel groups (16 lanes each); lane scans its pixel over t=64.
// 4 timesteps' spikes packed into one int (5-bit fields) before shfl reduce.
// Writes padded pooled2p at [Hg+3][Wg+3].
__global__ void __launch_bounds__(256) iaf1_pool2_kernel() {
    int warp_id = blockIdx.x * 8 + (threadIdx.x >> 5);
    int lane = threadIdx.x & 31;
    int g = warp_id * 2 + (lane >> 4);               // group in [0, 8192)
    int Wg = g & 15, Hg = (g >> 4) & 15, c = (g >> 8) & 3, n = g >> 10;
    int l = lane & 15;
    int h = Hg * 4 + (l >> 2), w = Wg * 4 + (l & 3);
    const float* src = g_h0 + (size_t)(((n * 4 + c) * 64 + h) * 64 + w) * 64;
    float* dst = g_pooled2p + (size_t)(((n * 4 + c) * 22 + Hg + 3) * 22 + Wg + 3) * 64;

    float v = 0.f;
#pragma unroll
    for (int tb = 0; tb < 16; tb++) {
        float4 x = *(const float4*)(src + tb * 4);
        float xv[4] = {x.x, x.y, x.z, x.w};
        int packed = 0;
#pragma unroll
        for (int k = 0; k < 4; k++) {
            v += xv[k];
            float s = (v >= 1.f) ? 1.f : 0.f;
            v -= s;
            packed |= (int)s << (5 * k);
        }
        // reduce over 16-lane group; fields max 16 < 32, no cross-field carry
        packed += __shfl_xor_sync(0xffffffffu, packed, 1);
        packed += __shfl_xor_sync(0xffffffffu, packed, 2);
        packed += __shfl_xor_sync(0xffffffffu, packed, 4);
        packed += __shfl_xor_sync(0xffffffffu, packed, 8);
        if (l == 0) {
            float4 o;
            o.x = (float)( packed        & 31) * 0.0625f;
            o.y = (float)((packed >> 5)  & 31) * 0.0625f;
            o.z = (float)((packed >> 10) & 31) * 0.0625f;
            o.w = (float)((packed >> 15) & 31) * 0.0625f;
            *(float4*)(dst + tb * 4) = o;
        }
    }
}

// ---------------- K4: conv7x7 pad3, 4->8 ch, 16x16, padded input, ci-split --
// block = (32 t-pairs, 4 w); thread computes acc[8 co] over 2 input channels.
// grid (4 wtiles, 16 h, 8 n * 2 halves) = 1024 blocks of 128 threads.
// half 0 -> ci {0,1} -> g_h1a;  half 1 -> ci {2,3} -> g_h1b.
__global__ void __launch_bounds__(128) conv2_kernel(const float* __restrict__ w1) {
    __shared__ ull sw[8][2][49];
    int half = blockIdx.z & 1;
    int n    = blockIdx.z >> 1;
    int tid = threadIdx.y * 32 + threadIdx.x;
    for (int i = tid; i < 8 * 2 * 49; i += 128) {
        int co  = i / 98;
        int rem = i % 98;
        int cih = rem / 49;
        int tap = rem % 49;
        ((ull*)sw)[i] = bcast2(w1[(co * 4 + half * 2 + cih) * 49 + tap]);
    }
    __syncthreads();

    int tp = threadIdx.x;
    int w  = blockIdx.x * 4 + threadIdx.y;   // 0..15
    int h  = blockIdx.y;                     // 0..15

    ull acc[8];
#pragma unroll
    for (int a = 0; a < 8; a++) acc[a] = 0ull;

#pragma unroll
    for (int cih = 0; cih < 2; cih++) {
        const float* base = g_pooled2p + (size_t)(n * 4 + half * 2 + cih) * 22 * 22 * 64;
#pragma unroll
        for (int r = 0; r < 7; r++) {        // padded rows h+0 .. h+6
            const float* rowp = base + (((h + r) * 22) + w) * 64 + tp * 2;
            ull v[7];
#pragma unroll
            for (int kx = 0; kx < 7; kx++)
                v[kx] = *(const ull*)(rowp + kx * 64);
#pragma unroll
            for (int co = 0; co < 8; co++)
#pragma unroll
                for (int kx = 0; kx < 7; kx++)
                    acc[co] = fma2(v[kx], sw[co][cih][r * 7 + kx], acc[co]);
        }
    }
    float* dst = half ? g_h1b : g_h1a;
#pragma unroll
    for (int co = 0; co < 8; co++)
        *(ull*)(dst + (size_t)(((n * 8 + co) * 16 + h) * 16 + w) * 64 + tp * 2) = acc[co];
}

// ---------------- K5: IAF + avgpool4, stage 2 (sums the two partials) -------
__global__ void __launch_bounds__(256) iaf2_pool3_kernel() {
    int warp_id = blockIdx.x * 8 + (threadIdx.x >> 5);
    int lane = threadIdx.x & 31;
    int g = warp_id * 2 + (lane >> 4);               // group in [0, 1024)
    int Wg = g & 3, Hg = (g >> 2) & 3, c = (g >> 4) & 7, n = g >> 7;
    int l = lane & 15;
    int h = Hg * 4 + (l >> 2), w = Wg * 4 + (l & 3);
    size_t off = (size_t)(((n * 8 + c) * 16 + h) * 16 + w) * 64;
    const float* srca = g_h1a + off;
    const float* srcb = g_h1b + off;
    float* dst = g_pooled3 + (size_t)(((n * 8 + c) * 4 + Hg) * 4 + Wg) * 64;

    float v = 0.f;
#pragma unroll
    for (int tb = 0; tb < 16; tb++) {
        float4 xa = *(const float4*)(srca + tb * 4);
        float4 xb = *(const float4*)(srcb + tb * 4);
        float xv[4] = {xa.x + xb.x, xa.y + xb.y, xa.z + xb.z, xa.w + xb.w};
        int packed = 0;
#pragma unroll
        for (int k = 0; k < 4; k++) {
            v += xv[k];
            float s = (v >= 1.f) ? 1.f : 0.f;
            v -= s;
            packed |= (int)s << (5 * k);
        }
        packed += __shfl_xor_sync(0xffffffffu, packed, 1);
        packed += __shfl_xor_sync(0xffffffffu, packed, 2);
        packed += __shfl_xor_sync(0xffffffffu, packed, 4);
        packed += __shfl_xor_sync(0xffffffffu, packed, 8);
        if (l == 0) {
            float4 o;
            o.x = (float)( packed        & 31) * 0.0625f;
            o.y = (float)((packed >> 5)  & 31) * 0.0625f;
            o.z = (float)((packed >> 10) & 31) * 0.0625f;
            o.w = (float)((packed >> 15) & 31) * 0.0625f;
            *(float4*)(dst + tb * 4) = o;
        }
    }
}

// ---------------- K6: feat(128) @ wl.T -> out (n,2,t) ------------------------
__global__ void __launch_bounds__(512) linear_kernel(const float* __restrict__ wl,
                                                     float* __restrict__ out) {
    int tid = threadIdx.x;
    __shared__ float swl[256];
    if (tid < 256) swl[tid] = wl[tid];
    __syncthreads();
    int t = tid & 63;
    int n = tid >> 6;
    const float* p = g_pooled3 + n * 128 * 64 + t;
    float a0 = 0.f, a1 = 0.f;
#pragma unroll
    for (int f = 0; f < 128; f++) {
        float v = p[f * 64];
        a0 += v * swl[f];
        a1 += v * swl[128 + f];
    }
    out[(n * 2 + 0) * 64 + t] = a0;
    out[(n * 2 + 1) * 64 + t] = a1;
}

// ---------------- launch ------------------------------------------------------
extern "C" void kernel_launch(void* const* d_in, const int* in_sizes, int n_in,
                              void* d_out, int out_size) {
    const float* inp = (const float*)d_in[0];   // (8,2,256,256,64)
    const float* w0  = (const float*)d_in[1];   // (4,2,7,7)
    const float* w1  = (const float*)d_in[2];   // (8,4,7,7)
    const float* wl  = (const float*)d_in[3];   // (2,128)
    float* out = (float*)d_out;                 // (8,2,64)

    pool1_kernel     <<<4096, 256>>>(inp);
    conv1_kernel     <<<dim3(8, 16, 8),  dim3(32, 8)>>>(w0);
    iaf1_pool2_kernel<<<512, 256>>>();
    conv2_kernel     <<<dim3(4, 16, 16), dim3(32, 4)>>>(w1);
    iaf2_pool3_kernel<<<64, 256>>>();
    linear_kernel    <<<1, 512>>>(wl, out);
}